// round 11
// baseline (speedup 1.0000x reference)
#include <cuda_runtime.h>
#include <cuda_fp16.h>
#include <cstdint>
#include <math.h>

#define NDIM 4096

// ---------------- device scratch (no allocs allowed) ------------------------
__device__ float  g_sq[NDIM];
__device__ __half g_xh    [(size_t)NDIM * NDIM];   // x  fp16 [B,F]
__device__ __half g_xth   [(size_t)NDIM * NDIM];   // x^T fp16 [F,B]
__device__ __half g_wouth [(size_t)NDIM * NDIM];   // W_out fp16 [OUT,F]
__device__ __half g_gramh [(size_t)NDIM * NDIM];   // gram fp16
__device__ __half g_mixedh[(size_t)NDIM * NDIM];   // mixed fp16

// ---------------- helpers ---------------------------------------------------
__device__ __forceinline__ uint32_t smem_u32(const void* p) {
    uint32_t a;
    asm("{ .reg .u64 t; cvta.to.shared.u64 t, %1; cvt.u32.u64 %0, t; }"
        : "=r"(a) : "l"(p));
    return a;
}
__device__ __forceinline__ void cp16(uint32_t dst, const void* src) {
    asm volatile("cp.async.cg.shared.global [%0], [%1], 16;"
                 :: "r"(dst), "l"(src) : "memory");
}
__device__ __forceinline__ void cp_commit() {
    asm volatile("cp.async.commit_group;" ::: "memory");
}
__device__ __forceinline__ void cp_wait1() {
    asm volatile("cp.async.wait_group 1;" ::: "memory");
}
__device__ __forceinline__ uint32_t swz128(uint32_t off) {
    return off ^ ((off >> 3) & 0x70);          // SW128, 128B rows
}
__device__ __forceinline__ void ldsm4(uint32_t& r0, uint32_t& r1,
                                      uint32_t& r2, uint32_t& r3, uint32_t a) {
    asm volatile("ldmatrix.sync.aligned.m8n8.x4.shared.b16 {%0,%1,%2,%3}, [%4];"
                 : "=r"(r0), "=r"(r1), "=r"(r2), "=r"(r3) : "r"(a));
}
__device__ __forceinline__ void mma16816(float* c, const uint32_t* a,
                                         const uint32_t* b) {
    asm volatile(
        "mma.sync.aligned.m16n8k16.row.col.f32.f16.f16.f32 "
        "{%0,%1,%2,%3}, {%4,%5,%6,%7}, {%8,%9}, {%0,%1,%2,%3};"
        : "+f"(c[0]), "+f"(c[1]), "+f"(c[2]), "+f"(c[3])
        : "r"(a[0]), "r"(a[1]), "r"(a[2]), "r"(a[3]), "r"(b[0]), "r"(b[1]));
}

// ---------------- GEMM config ----------------------------------------------
// 128 threads/CTA (4 warps), warp tile 64x64 -> LDSM traffic 4 B/out/iter
// (vs 6 with 64x32): the smem crossbar was the binding resource.
// launch_bounds(128,2): reg cap 256 (no spill), 2 CTAs/SM (decoupled barriers).
constexpr int BM = 128, BN = 128, BK = 64;     // BK halves = 128 B rows (SW128)
constexpr int NITER = NDIM / BK;               // 64
constexpr int A_BYTES = BM * BK * 2;           // 16384
constexpr int B_BYTES = BN * BK * 2;           // 16384
constexpr int STAGE_BYTES = A_BYTES + B_BYTES; // 32768
constexpr int NSTAGE = 3;
constexpr int SMEM_TOTAL = NSTAGE * STAGE_BYTES;   // 98304 (x2 CTAs = 192K/SM)
constexpr int NTILE = NDIM / BM;               // 32
constexpr int TRI_BLOCKS = NTILE * (NTILE + 1) / 2;   // 528
constexpr int DPAD = 129;                      // smem_d row pad (floats)

// MODE 0: S = x x^T (upper-tri tiles only) + dist/exp -> g_gramh (+mirror)
// MODE 1: mixed = gram @ x (B = x^T)   -> g_mixedh
// MODE 2: out = mixed @ W_out^T + b    -> Cext (fp32)
template <int MODE>
__global__ void __launch_bounds__(128, 2)
hmma_gemm(const float* __restrict__ aux, float* __restrict__ Cext)
{
    extern __shared__ __align__(1024) char smem[];
    const uint32_t sb = smem_u32(smem);

    const int tid = threadIdx.x, wid = tid >> 5, lane = tid & 31;
    int bm, bn;
    if (MODE == 0) {
        // decode linear block id -> upper-triangular tile (i, j), j >= i
        int rem = blockIdx.x, i = 0;
        while (rem >= NTILE - i) { rem -= NTILE - i; i++; }
        bm = i * BM;
        bn = (i + rem) * BN;
    } else {
        bm = blockIdx.y * BM;
        bn = blockIdx.x * BN;
    }
    const int wm = (wid >> 1) * 64;      // 2 warps along M
    const int wn = (wid & 1) * 64;       // 2 warps along N

    const __half* Ag = (MODE == 0) ? g_xh : (MODE == 1) ? g_gramh : g_mixedh;
    const __half* Bg = (MODE == 0) ? g_xh : (MODE == 1) ? g_xth   : g_wouth;

    // cp.async mapping: 1024 16B chunks per tile, 128 threads -> 8 chunks each.
    // Thread base: row r0 = tid>>3 (0..15), colgroup c0 = tid&7; chunk t adds
    // 16 rows. row&7 is invariant under +16t, so swizzled smem offset is just
    // sA0 + t*2048 (t*2048 only touches bits >= 11).
    const int r0 = tid >> 3, c0 = tid & 7;
    const __half* gA0 = Ag + (size_t)(bm + r0) * NDIM + c0 * 8;
    const __half* gB0 = Bg + (size_t)(bn + r0) * NDIM + c0 * 8;
    const uint32_t s0 = swz128((uint32_t)r0 * 128 + c0 * 16);

    // ldmatrix lane offsets (bytes, pre-swizzle), 128B rows.
    // Swizzle is always applied to the FULL offset (incl. ks*32).
    const uint32_t aRB = (uint32_t)(wm + (lane & 15)) * 128 + (lane >> 4) * 16;
    const uint32_t bRB = (uint32_t)(wn + (lane & 7) + ((lane >> 4) << 3)) * 128 +
                         ((lane >> 3) & 1) * 16;

    float acc[4][8][4];
#pragma unroll
    for (int i = 0; i < 4; i++)
#pragma unroll
        for (int j = 0; j < 8; j++)
#pragma unroll
            for (int q = 0; q < 4; q++) acc[i][j][q] = 0.f;

    // prologue: stages 0,1
#pragma unroll
    for (int t = 0; t < 2; t++) {
        const uint32_t base = sb + t * STAGE_BYTES;
        const int kt = t * BK;
#pragma unroll
        for (int q = 0; q < 8; q++) {
            cp16(base + s0 + q * 2048,           gA0 + (size_t)q * 16 * NDIM + kt);
            cp16(base + A_BYTES + s0 + q * 2048, gB0 + (size_t)q * 16 * NDIM + kt);
        }
        cp_commit();
    }

    for (int it = 0; it < NITER; ++it) {
        cp_wait1();
        __syncthreads();

        const int nt = it + 2;
        if (nt < NITER) {
            const uint32_t base = sb + (nt % 3) * STAGE_BYTES;
            const int kt = nt * BK;
#pragma unroll
            for (int q = 0; q < 8; q++) {
                cp16(base + s0 + q * 2048,           gA0 + (size_t)q * 16 * NDIM + kt);
                cp16(base + A_BYTES + s0 + q * 2048, gB0 + (size_t)q * 16 * NDIM + kt);
            }
        }
        cp_commit();

        const uint32_t abase = sb + (it % 3) * STAGE_BYTES;
        const uint32_t bbase = abase + A_BYTES;

#pragma unroll
        for (int ks = 0; ks < 4; ks++) {
            uint32_t af[4][4], bf[8][2];
#pragma unroll
            for (int mf = 0; mf < 4; mf++)
                ldsm4(af[mf][0], af[mf][1], af[mf][2], af[mf][3],
                      abase + swz128(aRB + mf * 2048 + ks * 32));
#pragma unroll
            for (int nf2 = 0; nf2 < 4; nf2++) {
                uint32_t r0r, r1r, r2r, r3r;
                // B stored [N,K]: non-trans ldmatrix = correct mma B fragment
                ldsm4(r0r, r1r, r2r, r3r,
                      bbase + swz128(bRB + nf2 * 2048 + ks * 32));
                bf[2 * nf2][0] = r0r;     bf[2 * nf2][1] = r1r;
                bf[2 * nf2 + 1][0] = r2r; bf[2 * nf2 + 1][1] = r3r;
            }
#pragma unroll
            for (int mf = 0; mf < 4; mf++)
#pragma unroll
                for (int nf = 0; nf < 8; nf++)
                    mma16816(acc[mf][nf], af[mf], bf[nf]);
        }
    }

    // ---------------- epilogue (register accumulators) ----------------------
    const int rb = bm + wm + (lane >> 2);
    const int cb = bn + wn + (lane & 3) * 2;

    if (MODE == 0) {
        const bool diag = (bm == bn);
        float* smem_d = reinterpret_cast<float*>(smem);   // reuse stage buffers
        __syncthreads();   // mainloop LDSM done before smem_d overwrites stages

        float2 sqc[8];
#pragma unroll
        for (int nf = 0; nf < 8; nf++)
            sqc[nf] = *reinterpret_cast<const float2*>(&g_sq[cb + nf * 8]);
#pragma unroll
        for (int mf = 0; mf < 4; mf++)
#pragma unroll
            for (int rs = 0; rs < 2; rs++) {
                const int row = rb + mf * 16 + rs * 8;
                const int row_l = row - bm;
                const float sqi = g_sq[row];
                const float* wr = aux + (size_t)row * NDIM;
                __half* orow = g_gramh + (size_t)row * NDIM;
#pragma unroll
                for (int nf = 0; nf < 8; nf++) {
                    const int col = cb + nf * 8;
                    const int col_l = col - bn;
                    float2 w2 = *reinterpret_cast<const float2*>(&wr[col]);
                    float s0f = acc[mf][nf][rs * 2 + 0];
                    float s1f = acc[mf][nf][rs * 2 + 1];
                    float d0 = sqrtf(fmaxf(sqi + sqc[nf].x - 2.f * s0f, 0.f));
                    float d1 = sqrtf(fmaxf(sqi + sqc[nf].y - 2.f * s1f, 0.f));
                    __half2 h = __floats2half2_rn(__expf(-fabsf(w2.x) * d0),
                                                  __expf(-fabsf(w2.y) * d1));
                    *reinterpret_cast<__half2*>(&orow[col]) = h;
                    if (!diag) {
                        smem_d[row_l * DPAD + col_l]     = d0;
                        smem_d[row_l * DPAD + col_l + 1] = d1;
                    }
                }
            }

        if (!diag) {
            __syncthreads();
            // mirror pass: gram[bn+co][bm+r] = exp(-|W[bn+co][bm+r]|*d[r][co])
            // thread t: mirror row co = t, two 64-col halves
            const int co = tid;
            const float* wrow = aux + (size_t)(bn + co) * NDIM + bm;
            __half* grow = g_gramh + (size_t)(bn + co) * NDIM + bm;
#pragma unroll
            for (int half = 0; half < 2; half++) {
                const int rbase = half * 64;
                __align__(16) __half hb[64];
#pragma unroll
                for (int u = 0; u < 64; u += 4) {
                    float4 w4 = *reinterpret_cast<const float4*>(wrow + rbase + u);
                    float dd0 = smem_d[(rbase + u + 0) * DPAD + co];
                    float dd1 = smem_d[(rbase + u + 1) * DPAD + co];
                    float dd2 = smem_d[(rbase + u + 2) * DPAD + co];
                    float dd3 = smem_d[(rbase + u + 3) * DPAD + co];
                    hb[u + 0] = __float2half(__expf(-fabsf(w4.x) * dd0));
                    hb[u + 1] = __float2half(__expf(-fabsf(w4.y) * dd1));
                    hb[u + 2] = __float2half(__expf(-fabsf(w4.z) * dd2));
                    hb[u + 3] = __float2half(__expf(-fabsf(w4.w) * dd3));
                }
#pragma unroll
                for (int q = 0; q < 8; q++)
                    reinterpret_cast<uint4*>(grow + rbase)[q] =
                        reinterpret_cast<uint4*>(hb)[q];
            }
        }
    } else if (MODE == 1) {
#pragma unroll
        for (int mf = 0; mf < 4; mf++)
#pragma unroll
            for (int rs = 0; rs < 2; rs++) {
                const int row = rb + mf * 16 + rs * 8;
                __half* orow = g_mixedh + (size_t)row * NDIM;
#pragma unroll
                for (int nf = 0; nf < 8; nf++) {
                    __half2 h = __floats2half2_rn(acc[mf][nf][rs * 2 + 0],
                                                  acc[mf][nf][rs * 2 + 1]);
                    *reinterpret_cast<__half2*>(&orow[cb + nf * 8]) = h;
                }
            }
    } else {
        float2 bias2[8];
#pragma unroll
        for (int nf = 0; nf < 8; nf++)
            bias2[nf] = *reinterpret_cast<const float2*>(&aux[cb + nf * 8]);
#pragma unroll
        for (int mf = 0; mf < 4; mf++)
#pragma unroll
            for (int rs = 0; rs < 2; rs++) {
                const int row = rb + mf * 16 + rs * 8;
                float* orow = Cext + (size_t)row * NDIM;
#pragma unroll
                for (int nf = 0; nf < 8; nf++) {
                    float2 v;
                    v.x = acc[mf][nf][rs * 2 + 0] + bias2[nf].x;
                    v.y = acc[mf][nf][rs * 2 + 1] + bias2[nf].y;
                    *reinterpret_cast<float2*>(&orow[cb + nf * 8]) = v;
                }
            }
    }
}

// ---------------- prep kernels ---------------------------------------------
__global__ void rownorm_kernel(const float* __restrict__ x) {
    const int row = blockIdx.x;
    const float4* xr = reinterpret_cast<const float4*>(x + (size_t)row * NDIM);
    float s = 0.f;
    for (int i = threadIdx.x; i < NDIM / 4; i += blockDim.x) {
        float4 v = xr[i];
        s += v.x * v.x + v.y * v.y + v.z * v.z + v.w * v.w;
    }
    __shared__ float red[256];
    red[threadIdx.x] = s;
    __syncthreads();
    for (int off = 128; off > 0; off >>= 1) {
        if (threadIdx.x < off) red[threadIdx.x] += red[threadIdx.x + off];
        __syncthreads();
    }
    if (threadIdx.x == 0) g_sq[row] = red[0];
}

// fused: x -> g_xh (fp16) and g_xth (fp16 transpose), one read of x
__global__ void prep_x_kernel(const float* __restrict__ src) {
    __shared__ float t[32][33];
    const int bx = blockIdx.x * 32, by = blockIdx.y * 32;
    const int tx = threadIdx.x, ty = threadIdx.y;   // (32, 8)
#pragma unroll
    for (int j = 0; j < 32; j += 8) {
        float v = src[(size_t)(by + ty + j) * NDIM + bx + tx];
        t[ty + j][tx] = v;
        g_xh[(size_t)(by + ty + j) * NDIM + bx + tx] = __float2half(v);
    }
    __syncthreads();
#pragma unroll
    for (int j = 0; j < 32; j += 8)
        g_xth[(size_t)(bx + ty + j) * NDIM + by + tx] = __float2half(t[tx][ty + j]);
}

__global__ void conv_wout_kernel(const float* __restrict__ src) {
    size_t i = ((size_t)blockIdx.x * blockDim.x + threadIdx.x) * 8;
    const float4* s = reinterpret_cast<const float4*>(src + i);
    float4 a = s[0], b = s[1];
    __half2 h0 = __floats2half2_rn(a.x, a.y);
    __half2 h1 = __floats2half2_rn(a.z, a.w);
    __half2 h2 = __floats2half2_rn(b.x, b.y);
    __half2 h3 = __floats2half2_rn(b.z, b.w);
    uint4 o;
    o.x = *reinterpret_cast<uint32_t*>(&h0);
    o.y = *reinterpret_cast<uint32_t*>(&h1);
    o.z = *reinterpret_cast<uint32_t*>(&h2);
    o.w = *reinterpret_cast<uint32_t*>(&h3);
    *reinterpret_cast<uint4*>(g_wouth + i) = o;
}

// ---------------------------------------------------------------------------
extern "C" void kernel_launch(void* const* d_in, const int* in_sizes, int n_in,
                              void* d_out, int out_size)
{
    const float* x     = (const float*)d_in[0];
    const float* W_rbf = (const float*)d_in[1];
    const float* W_out = (const float*)d_in[2];
    const float* b_out = (const float*)d_in[3];
    float* out = (float*)d_out;

    static bool attr_done = false;
    if (!attr_done) {
        cudaFuncSetAttribute(hmma_gemm<0>, cudaFuncAttributeMaxDynamicSharedMemorySize, SMEM_TOTAL);
        cudaFuncSetAttribute(hmma_gemm<1>, cudaFuncAttributeMaxDynamicSharedMemorySize, SMEM_TOTAL);
        cudaFuncSetAttribute(hmma_gemm<2>, cudaFuncAttributeMaxDynamicSharedMemorySize, SMEM_TOTAL);
        attr_done = true;
    }

    rownorm_kernel<<<NDIM, 256>>>(x);
    prep_x_kernel<<<dim3(128, 128), dim3(32, 8)>>>(x);
    conv_wout_kernel<<<8192, 256>>>(W_out);

    dim3 grid(NDIM / BN, NDIM / BM);   // 32 x 32
    hmma_gemm<0><<<TRI_BLOCKS, 128, SMEM_TOTAL>>>(W_rbf, nullptr);
    hmma_gemm<1><<<grid, 128, SMEM_TOTAL>>>(nullptr, nullptr);
    hmma_gemm<2><<<grid, 128, SMEM_TOTAL>>>(b_out, out);
}

// round 12
// speedup vs baseline: 1.6709x; 1.6709x over previous
#include <cuda_runtime.h>
#include <cuda_fp16.h>
#include <cstdint>
#include <math.h>

#define NDIM 4096

// ---------------- device scratch (no allocs allowed) ------------------------
__device__ float  g_sq[NDIM];
__device__ __half g_xh    [(size_t)NDIM * NDIM];   // x  fp16 [B,F]
__device__ __half g_wouth [(size_t)NDIM * NDIM];   // W_out fp16 [OUT,F]
__device__ __half g_gramh [(size_t)NDIM * NDIM];   // gram fp16
__device__ __half g_qh    [(size_t)NDIM * NDIM];   // Q = W_out @ x^T fp16 [OUT,B]

// ---------------- helpers ---------------------------------------------------
__device__ __forceinline__ uint32_t smem_u32(const void* p) {
    uint32_t a;
    asm("{ .reg .u64 t; cvta.to.shared.u64 t, %1; cvt.u32.u64 %0, t; }"
        : "=r"(a) : "l"(p));
    return a;
}
__device__ __forceinline__ void cp16(uint32_t dst, const void* src) {
    asm volatile("cp.async.cg.shared.global [%0], [%1], 16;"
                 :: "r"(dst), "l"(src) : "memory");
}
__device__ __forceinline__ void cp_commit() {
    asm volatile("cp.async.commit_group;" ::: "memory");
}
__device__ __forceinline__ void cp_wait1() {
    asm volatile("cp.async.wait_group 1;" ::: "memory");
}
__device__ __forceinline__ uint32_t swz128(uint32_t off) {
    return off ^ ((off >> 3) & 0x70);          // SW128, 128B rows
}
__device__ __forceinline__ void ldsm4(uint32_t& r0, uint32_t& r1,
                                      uint32_t& r2, uint32_t& r3, uint32_t a) {
    asm volatile("ldmatrix.sync.aligned.m8n8.x4.shared.b16 {%0,%1,%2,%3}, [%4];"
                 : "=r"(r0), "=r"(r1), "=r"(r2), "=r"(r3) : "r"(a));
}
__device__ __forceinline__ void mma16816(float* c, const uint32_t* a,
                                         const uint32_t* b) {
    asm volatile(
        "mma.sync.aligned.m16n8k16.row.col.f32.f16.f16.f32 "
        "{%0,%1,%2,%3}, {%4,%5,%6,%7}, {%8,%9}, {%0,%1,%2,%3};"
        : "+f"(c[0]), "+f"(c[1]), "+f"(c[2]), "+f"(c[3])
        : "r"(a[0]), "r"(a[1]), "r"(a[2]), "r"(a[3]), "r"(b[0]), "r"(b[1]));
}

// ---------------- GEMM config (R10-proven shape) ----------------------------
constexpr int BM = 128, BN = 128, BK = 64;     // BK halves = 128 B rows (SW128)
constexpr int NITER = NDIM / BK;               // 64
constexpr int A_BYTES = BM * BK * 2;           // 16384
constexpr int B_BYTES = BN * BK * 2;           // 16384
constexpr int STAGE_BYTES = A_BYTES + B_BYTES; // 32768
constexpr int NSTAGE = 3;
constexpr int SMEM_TOTAL = NSTAGE * STAGE_BYTES;   // 98304 (x2 CTAs = 192K/SM)
constexpr int NTILE = NDIM / BM;               // 32
constexpr int TRI_BLOCKS = NTILE * (NTILE + 1) / 2;   // 528
constexpr int FUSED_BLOCKS = TRI_BLOCKS + NTILE * NTILE;  // 528 + 1024
constexpr int DPAD = 129;                      // smem_d row pad (floats)

// MODE 0 (fused): blocks [0,528): gram tri-tiles (S = x x^T + dist/exp, +mirror)
//                 blocks [528,1552): Q = W_out @ x^T  (NT, fp16 out)
// MODE 2: out = NT(gram, Q) + b  -> Cext (fp32)
template <int MODE>
__global__ void __launch_bounds__(256, 2)
hmma_gemm(const float* __restrict__ aux, float* __restrict__ Cext)
{
    extern __shared__ __align__(1024) char smem[];
    const uint32_t sb = smem_u32(smem);

    const int tid = threadIdx.x, wid = tid >> 5, lane = tid & 31;
    int bm, bn;
    bool gram_mode = false;
    if (MODE == 0) {
        if (blockIdx.x < TRI_BLOCKS) {
            gram_mode = true;
            int rem = blockIdx.x, i = 0;
            while (rem >= NTILE - i) { rem -= NTILE - i; i++; }
            bm = i * BM;
            bn = (i + rem) * BN;
        } else {
            int q = blockIdx.x - TRI_BLOCKS;
            bm = (q >> 5) * BM;
            bn = (q & 31) * BN;
        }
    } else {
        bm = blockIdx.y * BM;
        bn = blockIdx.x * BN;
    }
    const int wm = (wid >> 2) * 64;      // 2 warps along M
    const int wn = (wid & 3) * 32;       // 4 warps along N

    const __half* Ag = (MODE == 0) ? (gram_mode ? g_xh : g_wouth) : g_gramh;
    const __half* Bg = (MODE == 0) ? g_xh : g_qh;

    // cp.async mapping: A and B each 1024 16B chunks -> 4 chunks/thread each
    const __half* gA[4];
    const __half* gB[4];
    uint32_t sA[4];
#pragma unroll
    for (int t = 0; t < 4; t++) {
        int ch = tid + t * 256;
        int r = ch >> 3, c = ch & 7;
        gA[t] = Ag + (size_t)(bm + r) * NDIM + c * 8;
        gB[t] = Bg + (size_t)(bn + r) * NDIM + c * 8;
        sA[t] = swz128(r * 128 + c * 16);
    }

    // ldmatrix lane offsets (bytes, pre-swizzle), 128B rows.
    // Swizzle is always applied to the FULL offset (incl. ks*32).
    const uint32_t aRB = (uint32_t)(wm + (lane & 15)) * 128 + (lane >> 4) * 16;
    const uint32_t bRB = (uint32_t)(wn + (lane & 7) + ((lane >> 4) << 3)) * 128 +
                         ((lane >> 3) & 1) * 16;

    float acc[4][4][4];
#pragma unroll
    for (int i = 0; i < 4; i++)
#pragma unroll
        for (int j = 0; j < 4; j++)
#pragma unroll
            for (int q = 0; q < 4; q++) acc[i][j][q] = 0.f;

    // prologue: stages 0,1
#pragma unroll
    for (int t = 0; t < 2; t++) {
        const uint32_t base = sb + t * STAGE_BYTES;
        const int kt = t * BK;
#pragma unroll
        for (int q = 0; q < 4; q++) {
            cp16(base + sA[q], gA[q] + kt);
            cp16(base + A_BYTES + sA[q], gB[q] + kt);
        }
        cp_commit();
    }

    for (int it = 0; it < NITER; ++it) {
        cp_wait1();
        __syncthreads();

        const int nt = it + 2;
        if (nt < NITER) {
            const uint32_t base = sb + (nt % 3) * STAGE_BYTES;
            const int kt = nt * BK;
#pragma unroll
            for (int q = 0; q < 4; q++) {
                cp16(base + sA[q], gA[q] + kt);
                cp16(base + A_BYTES + sA[q], gB[q] + kt);
            }
        }
        cp_commit();

        const uint32_t abase = sb + (it % 3) * STAGE_BYTES;
        const uint32_t bbase = abase + A_BYTES;

#pragma unroll
        for (int ks = 0; ks < 4; ks++) {
            uint32_t af[4][4], bf[4][2];
#pragma unroll
            for (int mf = 0; mf < 4; mf++)
                ldsm4(af[mf][0], af[mf][1], af[mf][2], af[mf][3],
                      abase + swz128(aRB + mf * 2048 + ks * 32));
#pragma unroll
            for (int nf2 = 0; nf2 < 2; nf2++) {
                uint32_t r0, r1, r2, r3;
                // B stored [N,K]: non-trans ldmatrix = correct mma B fragment
                ldsm4(r0, r1, r2, r3,
                      bbase + swz128(bRB + nf2 * 2048 + ks * 32));
                bf[2 * nf2][0] = r0;     bf[2 * nf2][1] = r1;
                bf[2 * nf2 + 1][0] = r2; bf[2 * nf2 + 1][1] = r3;
            }
#pragma unroll
            for (int mf = 0; mf < 4; mf++)
#pragma unroll
                for (int nf = 0; nf < 4; nf++)
                    mma16816(acc[mf][nf], af[mf], bf[nf]);
        }
    }

    // ---------------- epilogue (register accumulators) ----------------------
    const int rb = bm + wm + (lane >> 2);
    const int cb = bn + wn + (lane & 3) * 2;

    if (MODE == 0 && gram_mode) {
        const bool diag = (bm == bn);
        float* smem_d = reinterpret_cast<float*>(smem);   // reuse stage buffers
        __syncthreads();   // mainloop LDSM done before smem_d overwrites stages

        float2 sqc[4];
#pragma unroll
        for (int nf = 0; nf < 4; nf++)
            sqc[nf] = *reinterpret_cast<const float2*>(&g_sq[cb + nf * 8]);
#pragma unroll
        for (int mf = 0; mf < 4; mf++)
#pragma unroll
            for (int rs = 0; rs < 2; rs++) {
                const int row = rb + mf * 16 + rs * 8;
                const int row_l = row - bm;
                const float sqi = g_sq[row];
                const float* wr = aux + (size_t)row * NDIM;
                __half* orow = g_gramh + (size_t)row * NDIM;
#pragma unroll
                for (int nf = 0; nf < 4; nf++) {
                    const int col = cb + nf * 8;
                    const int col_l = col - bn;
                    float2 w2 = *reinterpret_cast<const float2*>(&wr[col]);
                    float s0 = acc[mf][nf][rs * 2 + 0];
                    float s1 = acc[mf][nf][rs * 2 + 1];
                    float d0 = sqrtf(fmaxf(sqi + sqc[nf].x - 2.f * s0, 0.f));
                    float d1 = sqrtf(fmaxf(sqi + sqc[nf].y - 2.f * s1, 0.f));
                    __half2 h = __floats2half2_rn(__expf(-fabsf(w2.x) * d0),
                                                  __expf(-fabsf(w2.y) * d1));
                    *reinterpret_cast<__half2*>(&orow[col]) = h;
                    if (!diag) {
                        smem_d[row_l * DPAD + col_l]     = d0;
                        smem_d[row_l * DPAD + col_l + 1] = d1;
                    }
                }
            }

        if (!diag) {
            __syncthreads();
            // mirror pass: gram[bn+co][bm+r] = exp(-|W[bn+co][bm+r]|*d[r][co])
            const int co = tid >> 1;
            const int rhalf = (tid & 1) * 64;
            const float* wrow = aux + (size_t)(bn + co) * NDIM + bm + rhalf;
            __half* grow = g_gramh + (size_t)(bn + co) * NDIM + bm + rhalf;
            __align__(16) __half hb[64];
#pragma unroll
            for (int u = 0; u < 64; u += 4) {
                float4 w4 = *reinterpret_cast<const float4*>(wrow + u);
                float dd0 = smem_d[(rhalf + u + 0) * DPAD + co];
                float dd1 = smem_d[(rhalf + u + 1) * DPAD + co];
                float dd2 = smem_d[(rhalf + u + 2) * DPAD + co];
                float dd3 = smem_d[(rhalf + u + 3) * DPAD + co];
                hb[u + 0] = __float2half(__expf(-fabsf(w4.x) * dd0));
                hb[u + 1] = __float2half(__expf(-fabsf(w4.y) * dd1));
                hb[u + 2] = __float2half(__expf(-fabsf(w4.z) * dd2));
                hb[u + 3] = __float2half(__expf(-fabsf(w4.w) * dd3));
            }
#pragma unroll
            for (int q = 0; q < 8; q++)
                reinterpret_cast<uint4*>(grow)[q] =
                    reinterpret_cast<uint4*>(hb)[q];
        }
    } else if (MODE == 0) {
        // Q epilogue: fp16 store to g_qh
#pragma unroll
        for (int mf = 0; mf < 4; mf++)
#pragma unroll
            for (int rs = 0; rs < 2; rs++) {
                const int row = rb + mf * 16 + rs * 8;
                __half* orow = g_qh + (size_t)row * NDIM;
#pragma unroll
                for (int nf = 0; nf < 4; nf++) {
                    __half2 h = __floats2half2_rn(acc[mf][nf][rs * 2 + 0],
                                                  acc[mf][nf][rs * 2 + 1]);
                    *reinterpret_cast<__half2*>(&orow[cb + nf * 8]) = h;
                }
            }
    } else {
        float2 bias2[4];
#pragma unroll
        for (int nf = 0; nf < 4; nf++)
            bias2[nf] = *reinterpret_cast<const float2*>(&aux[cb + nf * 8]);
#pragma unroll
        for (int mf = 0; mf < 4; mf++)
#pragma unroll
            for (int rs = 0; rs < 2; rs++) {
                const int row = rb + mf * 16 + rs * 8;
                float* orow = Cext + (size_t)row * NDIM;
#pragma unroll
                for (int nf = 0; nf < 4; nf++) {
                    float2 v;
                    v.x = acc[mf][nf][rs * 2 + 0] + bias2[nf].x;
                    v.y = acc[mf][nf][rs * 2 + 1] + bias2[nf].y;
                    *reinterpret_cast<float2*>(&orow[cb + nf * 8]) = v;
                }
            }
    }
}

// ---------------- prep kernels ---------------------------------------------
__global__ void rownorm_kernel(const float* __restrict__ x) {
    const int row = blockIdx.x;
    const float4* xr = reinterpret_cast<const float4*>(x + (size_t)row * NDIM);
    float s = 0.f;
    for (int i = threadIdx.x; i < NDIM / 4; i += blockDim.x) {
        float4 v = xr[i];
        s += v.x * v.x + v.y * v.y + v.z * v.z + v.w * v.w;
    }
    __shared__ float red[256];
    red[threadIdx.x] = s;
    __syncthreads();
    for (int off = 128; off > 0; off >>= 1) {
        if (threadIdx.x < off) red[threadIdx.x] += red[threadIdx.x + off];
        __syncthreads();
    }
    if (threadIdx.x == 0) g_sq[row] = red[0];
}

template <int DST>   // 0 -> g_xh, 1 -> g_wouth
__global__ void conv_half_kernel(const float* __restrict__ src) {
    size_t i = ((size_t)blockIdx.x * blockDim.x + threadIdx.x) * 8;
    const float4* s = reinterpret_cast<const float4*>(src + i);
    float4 a = s[0], b = s[1];
    __half2 h0 = __floats2half2_rn(a.x, a.y);
    __half2 h1 = __floats2half2_rn(a.z, a.w);
    __half2 h2 = __floats2half2_rn(b.x, b.y);
    __half2 h3 = __floats2half2_rn(b.z, b.w);
    uint4 o;
    o.x = *reinterpret_cast<uint32_t*>(&h0);
    o.y = *reinterpret_cast<uint32_t*>(&h1);
    o.z = *reinterpret_cast<uint32_t*>(&h2);
    o.w = *reinterpret_cast<uint32_t*>(&h3);
    __half* dst = DST == 0 ? g_xh : g_wouth;
    *reinterpret_cast<uint4*>(dst + i) = o;
}

// ---------------------------------------------------------------------------
extern "C" void kernel_launch(void* const* d_in, const int* in_sizes, int n_in,
                              void* d_out, int out_size)
{
    const float* x     = (const float*)d_in[0];
    const float* W_rbf = (const float*)d_in[1];
    const float* W_out = (const float*)d_in[2];
    const float* b_out = (const float*)d_in[3];
    float* out = (float*)d_out;

    static bool attr_done = false;
    if (!attr_done) {
        cudaFuncSetAttribute(hmma_gemm<0>, cudaFuncAttributeMaxDynamicSharedMemorySize, SMEM_TOTAL);
        cudaFuncSetAttribute(hmma_gemm<2>, cudaFuncAttributeMaxDynamicSharedMemorySize, SMEM_TOTAL);
        attr_done = true;
    }

    rownorm_kernel<<<NDIM, 256>>>(x);
    conv_half_kernel<0><<<8192, 256>>>(x);
    conv_half_kernel<1><<<8192, 256>>>(W_out);

    // fused: gram (528 tri-tiles) + Q = W_out @ x^T (1024 tiles), one launch
    hmma_gemm<0><<<FUSED_BLOCKS, 256, SMEM_TOTAL>>>(W_rbf, nullptr);
    // final: out = NT(gram, Q) + b
    dim3 grid(NDIM / BN, NDIM / BM);   // 32 x 32
    hmma_gemm<2><<<grid, 256, SMEM_TOTAL>>>(b_out, out);
}

// round 13
// speedup vs baseline: 1.6893x; 1.0110x over previous
#include <cuda_runtime.h>
#include <cuda_fp16.h>
#include <cstdint>
#include <math.h>

#define NDIM 4096

// ---------------- device scratch (no allocs allowed) ------------------------
__device__ float  g_sq[NDIM];
__device__ __half g_xh    [(size_t)NDIM * NDIM];   // x  fp16 [B,F]
__device__ __half g_wouth [(size_t)NDIM * NDIM];   // W_out fp16 [OUT,F]
__device__ __half g_gramh [(size_t)NDIM * NDIM];   // gram fp16
__device__ __half g_qh    [(size_t)NDIM * NDIM];   // Q = W_out @ x^T fp16 [OUT,B]

// ---------------- helpers ---------------------------------------------------
__device__ __forceinline__ uint32_t smem_u32(const void* p) {
    uint32_t a;
    asm("{ .reg .u64 t; cvta.to.shared.u64 t, %1; cvt.u32.u64 %0, t; }"
        : "=r"(a) : "l"(p));
    return a;
}
__device__ __forceinline__ void cp16(uint32_t dst, const void* src) {
    asm volatile("cp.async.cg.shared.global [%0], [%1], 16;"
                 :: "r"(dst), "l"(src) : "memory");
}
__device__ __forceinline__ void cp_commit() {
    asm volatile("cp.async.commit_group;" ::: "memory");
}
__device__ __forceinline__ void cp_wait1() {
    asm volatile("cp.async.wait_group 1;" ::: "memory");
}
__device__ __forceinline__ uint32_t swz128(uint32_t off) {
    return off ^ ((off >> 3) & 0x70);          // SW128, 128B rows
}
__device__ __forceinline__ void ldsm4(uint32_t& r0, uint32_t& r1,
                                      uint32_t& r2, uint32_t& r3, uint32_t a) {
    asm volatile("ldmatrix.sync.aligned.m8n8.x4.shared.b16 {%0,%1,%2,%3}, [%4];"
                 : "=r"(r0), "=r"(r1), "=r"(r2), "=r"(r3) : "r"(a));
}
__device__ __forceinline__ void mma16816(float* c, const uint32_t* a,
                                         const uint32_t* b) {
    asm volatile(
        "mma.sync.aligned.m16n8k16.row.col.f32.f16.f16.f32 "
        "{%0,%1,%2,%3}, {%4,%5,%6,%7}, {%8,%9}, {%0,%1,%2,%3};"
        : "+f"(c[0]), "+f"(c[1]), "+f"(c[2]), "+f"(c[3])
        : "r"(a[0]), "r"(a[1]), "r"(a[2]), "r"(a[3]), "r"(b[0]), "r"(b[1]));
}

// ---------------- GEMM config (R10-proven shape) ----------------------------
constexpr int BM = 128, BN = 128, BK = 64;     // BK halves = 128 B rows (SW128)
constexpr int NITER = NDIM / BK;               // 64
constexpr int A_BYTES = BM * BK * 2;           // 16384
constexpr int B_BYTES = BN * BK * 2;           // 16384
constexpr int STAGE_BYTES = A_BYTES + B_BYTES; // 32768
constexpr int NSTAGE = 3;
constexpr int SMEM_TOTAL = NSTAGE * STAGE_BYTES;   // 98304 (x2 CTAs = 192K/SM)
constexpr int NTILE = NDIM / BM;               // 32
constexpr int TRI_BLOCKS = NTILE * (NTILE + 1) / 2;   // 528
constexpr int FUSED_BLOCKS = TRI_BLOCKS + NTILE * NTILE;  // 528 + 1024
constexpr int DPAD = 129;                      // smem_d row pad (floats)

// MODE 0 (fused): blocks [0,528): gram tri-tiles (S = x x^T + dist/exp, +mirror)
//                 blocks [528,1552): Q = W_out @ x^T  (NT, fp16 out)
// MODE 2: out = NT(gram, Q) + b  -> Cext (fp32)
template <int MODE>
__global__ void __launch_bounds__(256, 2)
hmma_gemm(const float* __restrict__ aux, float* __restrict__ Cext)
{
    extern __shared__ __align__(1024) char smem[];
    const uint32_t sb = smem_u32(smem);

    const int tid = threadIdx.x, wid = tid >> 5, lane = tid & 31;
    int bm, bn;
    bool gram_mode = false;
    if (MODE == 0) {
        if (blockIdx.x < TRI_BLOCKS) {
            gram_mode = true;
            int rem = blockIdx.x, i = 0;
            while (rem >= NTILE - i) { rem -= NTILE - i; i++; }
            bm = i * BM;
            bn = (i + rem) * BN;
        } else {
            int q = blockIdx.x - TRI_BLOCKS;
            bm = (q >> 5) * BM;
            bn = (q & 31) * BN;
        }
    } else {
        bm = blockIdx.y * BM;
        bn = blockIdx.x * BN;
    }
    const int wm = (wid >> 2) * 64;      // 2 warps along M
    const int wn = (wid & 3) * 32;       // 4 warps along N

    const __half* Ag = (MODE == 0) ? (gram_mode ? g_xh : g_wouth) : g_gramh;
    const __half* Bg = (MODE == 0) ? g_xh : g_qh;

    // cp.async mapping: A and B each 1024 16B chunks -> 4 chunks/thread each
    const __half* gA[4];
    const __half* gB[4];
    uint32_t sA[4];
#pragma unroll
    for (int t = 0; t < 4; t++) {
        int ch = tid + t * 256;
        int r = ch >> 3, c = ch & 7;
        gA[t] = Ag + (size_t)(bm + r) * NDIM + c * 8;
        gB[t] = Bg + (size_t)(bn + r) * NDIM + c * 8;
        sA[t] = swz128(r * 128 + c * 16);
    }

    // ldmatrix lane offsets (bytes, pre-swizzle), 128B rows.
    // Swizzle is always applied to the FULL offset (incl. ks*32).
    const uint32_t aRB = (uint32_t)(wm + (lane & 15)) * 128 + (lane >> 4) * 16;
    const uint32_t bRB = (uint32_t)(wn + (lane & 7) + ((lane >> 4) << 3)) * 128 +
                         ((lane >> 3) & 1) * 16;

    float acc[4][4][4];
#pragma unroll
    for (int i = 0; i < 4; i++)
#pragma unroll
        for (int j = 0; j < 4; j++)
#pragma unroll
            for (int q = 0; q < 4; q++) acc[i][j][q] = 0.f;

    // prologue: stages 0,1
#pragma unroll
    for (int t = 0; t < 2; t++) {
        const uint32_t base = sb + t * STAGE_BYTES;
        const int kt = t * BK;
#pragma unroll
        for (int q = 0; q < 4; q++) {
            cp16(base + sA[q], gA[q] + kt);
            cp16(base + A_BYTES + sA[q], gB[q] + kt);
        }
        cp_commit();
    }

    for (int it = 0; it < NITER; ++it) {
        cp_wait1();
        __syncthreads();

        const int nt = it + 2;
        if (nt < NITER) {
            const uint32_t base = sb + (nt % 3) * STAGE_BYTES;
            const int kt = nt * BK;
#pragma unroll
            for (int q = 0; q < 4; q++) {
                cp16(base + sA[q], gA[q] + kt);
                cp16(base + A_BYTES + sA[q], gB[q] + kt);
            }
        }
        cp_commit();

        const uint32_t abase = sb + (it % 3) * STAGE_BYTES;
        const uint32_t bbase = abase + A_BYTES;

#pragma unroll
        for (int ks = 0; ks < 4; ks++) {
            uint32_t af[4][4], bf[4][2];
#pragma unroll
            for (int mf = 0; mf < 4; mf++)
                ldsm4(af[mf][0], af[mf][1], af[mf][2], af[mf][3],
                      abase + swz128(aRB + mf * 2048 + ks * 32));
#pragma unroll
            for (int nf2 = 0; nf2 < 2; nf2++) {
                uint32_t r0, r1, r2, r3;
                // B stored [N,K]: non-trans ldmatrix = correct mma B fragment
                ldsm4(r0, r1, r2, r3,
                      bbase + swz128(bRB + nf2 * 2048 + ks * 32));
                bf[2 * nf2][0] = r0;     bf[2 * nf2][1] = r1;
                bf[2 * nf2 + 1][0] = r2; bf[2 * nf2 + 1][1] = r3;
            }
#pragma unroll
            for (int mf = 0; mf < 4; mf++)
#pragma unroll
                for (int nf = 0; nf < 4; nf++)
                    mma16816(acc[mf][nf], af[mf], bf[nf]);
        }
    }

    // ---------------- epilogue (register accumulators) ----------------------
    const int rb = bm + wm + (lane >> 2);
    const int cb = bn + wn + (lane & 3) * 2;

    if (MODE == 0 && gram_mode) {
        const bool diag = (bm == bn);
        float* smem_d = reinterpret_cast<float*>(smem);   // reuse stage buffers
        __syncthreads();   // mainloop LDSM done before smem_d overwrites stages

        float2 sqc[4];
#pragma unroll
        for (int nf = 0; nf < 4; nf++)
            sqc[nf] = *reinterpret_cast<const float2*>(&g_sq[cb + nf * 8]);
#pragma unroll
        for (int mf = 0; mf < 4; mf++)
#pragma unroll
            for (int rs = 0; rs < 2; rs++) {
                const int row = rb + mf * 16 + rs * 8;
                const int row_l = row - bm;
                const float sqi = g_sq[row];
                const float* wr = aux + (size_t)row * NDIM;
                __half* orow = g_gramh + (size_t)row * NDIM;
#pragma unroll
                for (int nf = 0; nf < 4; nf++) {
                    const int col = cb + nf * 8;
                    const int col_l = col - bn;
                    float2 w2 = *reinterpret_cast<const float2*>(&wr[col]);
                    float s0 = acc[mf][nf][rs * 2 + 0];
                    float s1 = acc[mf][nf][rs * 2 + 1];
                    float d0 = sqrtf(fmaxf(sqi + sqc[nf].x - 2.f * s0, 0.f));
                    float d1 = sqrtf(fmaxf(sqi + sqc[nf].y - 2.f * s1, 0.f));
                    __half2 h = __floats2half2_rn(__expf(-fabsf(w2.x) * d0),
                                                  __expf(-fabsf(w2.y) * d1));
                    *reinterpret_cast<__half2*>(&orow[col]) = h;
                    if (!diag) {
                        smem_d[row_l * DPAD + col_l]     = d0;
                        smem_d[row_l * DPAD + col_l + 1] = d1;
                    }
                }
            }

        if (!diag) {
            __syncthreads();
            // mirror pass: gram[bn+co][bm+r] = exp(-|W[bn+co][bm+r]|*d[r][co])
            const int co = tid >> 1;
            const int rhalf = (tid & 1) * 64;
            const float* wrow = aux + (size_t)(bn + co) * NDIM + bm + rhalf;
            __half* grow = g_gramh + (size_t)(bn + co) * NDIM + bm + rhalf;
            __align__(16) __half hb[64];
#pragma unroll
            for (int u = 0; u < 64; u += 4) {
                float4 w4 = *reinterpret_cast<const float4*>(wrow + u);
                float dd0 = smem_d[(rhalf + u + 0) * DPAD + co];
                float dd1 = smem_d[(rhalf + u + 1) * DPAD + co];
                float dd2 = smem_d[(rhalf + u + 2) * DPAD + co];
                float dd3 = smem_d[(rhalf + u + 3) * DPAD + co];
                hb[u + 0] = __float2half(__expf(-fabsf(w4.x) * dd0));
                hb[u + 1] = __float2half(__expf(-fabsf(w4.y) * dd1));
                hb[u + 2] = __float2half(__expf(-fabsf(w4.z) * dd2));
                hb[u + 3] = __float2half(__expf(-fabsf(w4.w) * dd3));
            }
#pragma unroll
            for (int q = 0; q < 8; q++)
                reinterpret_cast<uint4*>(grow)[q] =
                    reinterpret_cast<uint4*>(hb)[q];
        }
    } else if (MODE == 0) {
        // Q epilogue: fp16 store to g_qh
#pragma unroll
        for (int mf = 0; mf < 4; mf++)
#pragma unroll
            for (int rs = 0; rs < 2; rs++) {
                const int row = rb + mf * 16 + rs * 8;
                __half* orow = g_qh + (size_t)row * NDIM;
#pragma unroll
                for (int nf = 0; nf < 4; nf++) {
                    __half2 h = __floats2half2_rn(acc[mf][nf][rs * 2 + 0],
                                                  acc[mf][nf][rs * 2 + 1]);
                    *reinterpret_cast<__half2*>(&orow[cb + nf * 8]) = h;
                }
            }
    } else {
        float2 bias2[4];
#pragma unroll
        for (int nf = 0; nf < 4; nf++)
            bias2[nf] = *reinterpret_cast<const float2*>(&aux[cb + nf * 8]);
#pragma unroll
        for (int mf = 0; mf < 4; mf++)
#pragma unroll
            for (int rs = 0; rs < 2; rs++) {
                const int row = rb + mf * 16 + rs * 8;
                float* orow = Cext + (size_t)row * NDIM;
#pragma unroll
                for (int nf = 0; nf < 4; nf++) {
                    float2 v;
                    v.x = acc[mf][nf][rs * 2 + 0] + bias2[nf].x;
                    v.y = acc[mf][nf][rs * 2 + 1] + bias2[nf].y;
                    *reinterpret_cast<float2*>(&orow[cb + nf * 8]) = v;
                }
            }
    }
}

// ---------------- prep kernels ---------------------------------------------
// fused: one block per row of x — read fp32 row ONCE, emit fp16 row + ||x||^2
__global__ void prep_x_kernel(const float* __restrict__ x) {
    const int row = blockIdx.x;
    const float4* xr = reinterpret_cast<const float4*>(x + (size_t)row * NDIM);
    uint4* hr = reinterpret_cast<uint4*>(g_xh + (size_t)row * NDIM);
    float s = 0.f;
#pragma unroll
    for (int t = 0; t < 2; t++) {
        int i = threadIdx.x + t * 256;           // float4 index, 2 per thread
        float4 a = xr[2 * i], b = xr[2 * i + 1];
        s += a.x * a.x + a.y * a.y + a.z * a.z + a.w * a.w
           + b.x * b.x + b.y * b.y + b.z * b.z + b.w * b.w;
        __half2 h0 = __floats2half2_rn(a.x, a.y);
        __half2 h1 = __floats2half2_rn(a.z, a.w);
        __half2 h2 = __floats2half2_rn(b.x, b.y);
        __half2 h3 = __floats2half2_rn(b.z, b.w);
        uint4 o;
        o.x = *reinterpret_cast<uint32_t*>(&h0);
        o.y = *reinterpret_cast<uint32_t*>(&h1);
        o.z = *reinterpret_cast<uint32_t*>(&h2);
        o.w = *reinterpret_cast<uint32_t*>(&h3);
        hr[i] = o;
    }
    __shared__ float red[256];
    red[threadIdx.x] = s;
    __syncthreads();
    for (int off = 128; off > 0; off >>= 1) {
        if (threadIdx.x < off) red[threadIdx.x] += red[threadIdx.x + off];
        __syncthreads();
    }
    if (threadIdx.x == 0) g_sq[row] = red[0];
}

__global__ void conv_wout_kernel(const float* __restrict__ src) {
    size_t i = ((size_t)blockIdx.x * blockDim.x + threadIdx.x) * 8;
    const float4* s = reinterpret_cast<const float4*>(src + i);
    float4 a = s[0], b = s[1];
    __half2 h0 = __floats2half2_rn(a.x, a.y);
    __half2 h1 = __floats2half2_rn(a.z, a.w);
    __half2 h2 = __floats2half2_rn(b.x, b.y);
    __half2 h3 = __floats2half2_rn(b.z, b.w);
    uint4 o;
    o.x = *reinterpret_cast<uint32_t*>(&h0);
    o.y = *reinterpret_cast<uint32_t*>(&h1);
    o.z = *reinterpret_cast<uint32_t*>(&h2);
    o.w = *reinterpret_cast<uint32_t*>(&h3);
    *reinterpret_cast<uint4*>(g_wouth + i) = o;
}

// ---------------------------------------------------------------------------
extern "C" void kernel_launch(void* const* d_in, const int* in_sizes, int n_in,
                              void* d_out, int out_size)
{
    const float* x     = (const float*)d_in[0];
    const float* W_rbf = (const float*)d_in[1];
    const float* W_out = (const float*)d_in[2];
    const float* b_out = (const float*)d_in[3];
    float* out = (float*)d_out;

    static bool attr_done = false;
    if (!attr_done) {
        cudaFuncSetAttribute(hmma_gemm<0>, cudaFuncAttributeMaxDynamicSharedMemorySize, SMEM_TOTAL);
        cudaFuncSetAttribute(hmma_gemm<2>, cudaFuncAttributeMaxDynamicSharedMemorySize, SMEM_TOTAL);
        attr_done = true;
    }

    prep_x_kernel<<<NDIM, 256>>>(x);        // x -> fp16 + row norms, one read
    conv_wout_kernel<<<8192, 256>>>(W_out);

    // fused: gram (528 tri-tiles) + Q = W_out @ x^T (1024 tiles), one launch
    hmma_gemm<0><<<FUSED_BLOCKS, 256, SMEM_TOTAL>>>(W_rbf, nullptr);
    // final: out = NT(gram, Q) + b
    dim3 grid(NDIM / BN, NDIM / BM);   // 32 x 32
    hmma_gemm<2><<<grid, 256, SMEM_TOTAL>>>(b_out, out);
}

// round 16
// speedup vs baseline: 1.6928x; 1.0021x over previous
#include <cuda_runtime.h>
#include <cuda_fp16.h>
#include <cstdint>
#include <math.h>

#define NDIM 4096

// ---------------- device scratch (no allocs allowed) ------------------------
__device__ float  g_sq[NDIM];
__device__ __half g_xh    [(size_t)NDIM * NDIM];   // x  fp16 [B,F]
__device__ __half g_wouth [(size_t)NDIM * NDIM];   // W_out fp16 [OUT,F]
__device__ __half g_gramh [(size_t)NDIM * NDIM];   // gram fp16
__device__ __half g_qh    [(size_t)NDIM * NDIM];   // Q = W_out @ x^T fp16 [OUT,B]

// ---------------- helpers ---------------------------------------------------
__device__ __forceinline__ uint32_t smem_u32(const void* p) {
    uint32_t a;
    asm("{ .reg .u64 t; cvta.to.shared.u64 t, %1; cvt.u32.u64 %0, t; }"
        : "=r"(a) : "l"(p));
    return a;
}
__device__ __forceinline__ void cp16(uint32_t dst, const void* src) {
    asm volatile("cp.async.cg.shared.global [%0], [%1], 16;"
                 :: "r"(dst), "l"(src) : "memory");
}
__device__ __forceinline__ void cp_commit() {
    asm volatile("cp.async.commit_group;" ::: "memory");
}
__device__ __forceinline__ void cp_wait1() {
    asm volatile("cp.async.wait_group 1;" ::: "memory");
}
__device__ __forceinline__ uint32_t swz128(uint32_t off) {
    return off ^ ((off >> 3) & 0x70);          // SW128, 128B rows
}
__device__ __forceinline__ void ldsm4(uint32_t& r0, uint32_t& r1,
                                      uint32_t& r2, uint32_t& r3, uint32_t a) {
    asm volatile("ldmatrix.sync.aligned.m8n8.x4.shared.b16 {%0,%1,%2,%3}, [%4];"
                 : "=r"(r0), "=r"(r1), "=r"(r2), "=r"(r3) : "r"(a));
}
__device__ __forceinline__ void mma16816(float* c, const uint32_t* a,
                                         const uint32_t* b) {
    asm volatile(
        "mma.sync.aligned.m16n8k16.row.col.f32.f16.f16.f32 "
        "{%0,%1,%2,%3}, {%4,%5,%6,%7}, {%8,%9}, {%0,%1,%2,%3};"
        : "+f"(c[0]), "+f"(c[1]), "+f"(c[2]), "+f"(c[3])
        : "r"(a[0]), "r"(a[1]), "r"(a[2]), "r"(a[3]), "r"(b[0]), "r"(b[1]));
}

// ---------------- GEMM config (R10-proven shape) ----------------------------
constexpr int BM = 128, BN = 128, BK = 64;     // BK halves = 128 B rows (SW128)
constexpr int NITER = NDIM / BK;               // 64
constexpr int A_BYTES = BM * BK * 2;           // 16384
constexpr int B_BYTES = BN * BK * 2;           // 16384
constexpr int STAGE_BYTES = A_BYTES + B_BYTES; // 32768
constexpr int NSTAGE = 3;
constexpr int SMEM_TOTAL = NSTAGE * STAGE_BYTES;   // 98304 (x2 CTAs = 192K/SM)
constexpr int NTILE = NDIM / BM;               // 32
constexpr int TRI_BLOCKS = NTILE * (NTILE + 1) / 2;   // 528
constexpr int FUSED_BLOCKS = TRI_BLOCKS + NTILE * NTILE;  // 528 + 1024
constexpr int DPAD = 129;                      // smem_d row pad (floats)

// MODE 0 (fused): blocks [0,528): gram tri-tiles (S = x x^T + dist/exp, +mirror)
//                 blocks [528,1552): Q = W_out @ x^T  (NT, fp16 out)
// MODE 2: out = NT(gram, Q) + b  -> Cext (fp32)
template <int MODE>
__global__ void __launch_bounds__(256, 2)
hmma_gemm(const float* __restrict__ aux, float* __restrict__ Cext)
{
    extern __shared__ __align__(1024) char smem[];
    const uint32_t sb = smem_u32(smem);

    const int tid = threadIdx.x, wid = tid >> 5, lane = tid & 31;
    int bm, bn;
    bool gram_mode = false;
    if (MODE == 0) {
        if (blockIdx.x < TRI_BLOCKS) {
            gram_mode = true;
            int rem = blockIdx.x, i = 0;
            while (rem >= NTILE - i) { rem -= NTILE - i; i++; }
            bm = i * BM;
            bn = (i + rem) * BN;
        } else {
            int q = blockIdx.x - TRI_BLOCKS;
            bm = (q >> 5) * BM;
            bn = (q & 31) * BN;
        }
    } else {
        bm = blockIdx.y * BM;
        bn = blockIdx.x * BN;
    }
    const int wm = (wid >> 2) * 64;      // 2 warps along M
    const int wn = (wid & 3) * 32;       // 4 warps along N

    const __half* Ag = (MODE == 0) ? (gram_mode ? g_xh : g_wouth) : g_gramh;
    const __half* Bg = (MODE == 0) ? g_xh : g_qh;

    // cp.async mapping: A and B each 1024 16B chunks -> 4 chunks/thread each
    const __half* gA[4];
    const __half* gB[4];
    uint32_t sA[4];
#pragma unroll
    for (int t = 0; t < 4; t++) {
        int ch = tid + t * 256;
        int r = ch >> 3, c = ch & 7;
        gA[t] = Ag + (size_t)(bm + r) * NDIM + c * 8;
        gB[t] = Bg + (size_t)(bn + r) * NDIM + c * 8;
        sA[t] = swz128(r * 128 + c * 16);
    }

    // ldmatrix lane offsets (bytes, pre-swizzle), 128B rows.
    // Swizzle is always applied to the FULL offset (incl. ks*32).
    const uint32_t aRB = (uint32_t)(wm + (lane & 15)) * 128 + (lane >> 4) * 16;
    const uint32_t bRB = (uint32_t)(wn + (lane & 7) + ((lane >> 4) << 3)) * 128 +
                         ((lane >> 3) & 1) * 16;

    float acc[4][4][4];
#pragma unroll
    for (int i = 0; i < 4; i++)
#pragma unroll
        for (int j = 0; j < 4; j++)
#pragma unroll
            for (int q = 0; q < 4; q++) acc[i][j][q] = 0.f;

    // prologue: stages 0,1
#pragma unroll
    for (int t = 0; t < 2; t++) {
        const uint32_t base = sb + t * STAGE_BYTES;
        const int kt = t * BK;
#pragma unroll
        for (int q = 0; q < 4; q++) {
            cp16(base + sA[q], gA[q] + kt);
            cp16(base + A_BYTES + sA[q], gB[q] + kt);
        }
        cp_commit();
    }

    for (int it = 0; it < NITER; ++it) {
        cp_wait1();
        __syncthreads();

        const int nt = it + 2;
        if (nt < NITER) {
            const uint32_t base = sb + (nt % 3) * STAGE_BYTES;
            const int kt = nt * BK;
#pragma unroll
            for (int q = 0; q < 4; q++) {
                cp16(base + sA[q], gA[q] + kt);
                cp16(base + A_BYTES + sA[q], gB[q] + kt);
            }
        }
        cp_commit();

        const uint32_t abase = sb + (it % 3) * STAGE_BYTES;
        const uint32_t bbase = abase + A_BYTES;

#pragma unroll
        for (int ks = 0; ks < 4; ks++) {
            uint32_t af[4][4], bf[4][2];
#pragma unroll
            for (int mf = 0; mf < 4; mf++)
                ldsm4(af[mf][0], af[mf][1], af[mf][2], af[mf][3],
                      abase + swz128(aRB + mf * 2048 + ks * 32));
#pragma unroll
            for (int nf2 = 0; nf2 < 2; nf2++) {
                uint32_t r0, r1, r2, r3;
                // B stored [N,K]: non-trans ldmatrix = correct mma B fragment
                ldsm4(r0, r1, r2, r3,
                      bbase + swz128(bRB + nf2 * 2048 + ks * 32));
                bf[2 * nf2][0] = r0;     bf[2 * nf2][1] = r1;
                bf[2 * nf2 + 1][0] = r2; bf[2 * nf2 + 1][1] = r3;
            }
#pragma unroll
            for (int mf = 0; mf < 4; mf++)
#pragma unroll
                for (int nf = 0; nf < 4; nf++)
                    mma16816(acc[mf][nf], af[mf], bf[nf]);
        }
    }

    // ---------------- epilogue (register accumulators) ----------------------
    const int rb = bm + wm + (lane >> 2);
    const int cb = bn + wn + (lane & 3) * 2;

    if (MODE == 0 && gram_mode) {
        const bool diag = (bm == bn);
        float* smem_d = reinterpret_cast<float*>(smem);   // reuse stage buffers
        __syncthreads();   // mainloop LDSM done before smem_d overwrites stages

        float2 sqc[4];
#pragma unroll
        for (int nf = 0; nf < 4; nf++)
            sqc[nf] = *reinterpret_cast<const float2*>(&g_sq[cb + nf * 8]);
#pragma unroll
        for (int mf = 0; mf < 4; mf++)
#pragma unroll
            for (int rs = 0; rs < 2; rs++) {
                const int row = rb + mf * 16 + rs * 8;
                const int row_l = row - bm;
                const float sqi = g_sq[row];
                const float* wr = aux + (size_t)row * NDIM;
                __half* orow = g_gramh + (size_t)row * NDIM;
#pragma unroll
                for (int nf = 0; nf < 4; nf++) {
                    const int col = cb + nf * 8;
                    const int col_l = col - bn;
                    float2 w2 = *reinterpret_cast<const float2*>(&wr[col]);
                    float s0 = acc[mf][nf][rs * 2 + 0];
                    float s1 = acc[mf][nf][rs * 2 + 1];
                    float d0 = sqrtf(fmaxf(sqi + sqc[nf].x - 2.f * s0, 0.f));
                    float d1 = sqrtf(fmaxf(sqi + sqc[nf].y - 2.f * s1, 0.f));
                    __half2 h = __floats2half2_rn(__expf(-fabsf(w2.x) * d0),
                                                  __expf(-fabsf(w2.y) * d1));
                    *reinterpret_cast<__half2*>(&orow[col]) = h;
                    if (!diag) {
                        smem_d[row_l * DPAD + col_l]     = d0;
                        smem_d[row_l * DPAD + col_l + 1] = d1;
                    }
                }
            }

        if (!diag) {
            __syncthreads();
            // mirror pass: gram[bn+co][bm+r] = exp(-|W[bn+co][bm+r]|*d[r][co])
            const int co = tid >> 1;
            const int rhalf = (tid & 1) * 64;
            const float* wrow = aux + (size_t)(bn + co) * NDIM + bm + rhalf;
            __half* grow = g_gramh + (size_t)(bn + co) * NDIM + bm + rhalf;
            __align__(16) __half hb[64];
#pragma unroll
            for (int u = 0; u < 64; u += 4) {
                float4 w4 = *reinterpret_cast<const float4*>(wrow + u);
                float dd0 = smem_d[(rhalf + u + 0) * DPAD + co];
                float dd1 = smem_d[(rhalf + u + 1) * DPAD + co];
                float dd2 = smem_d[(rhalf + u + 2) * DPAD + co];
                float dd3 = smem_d[(rhalf + u + 3) * DPAD + co];
                hb[u + 0] = __float2half(__expf(-fabsf(w4.x) * dd0));
                hb[u + 1] = __float2half(__expf(-fabsf(w4.y) * dd1));
                hb[u + 2] = __float2half(__expf(-fabsf(w4.z) * dd2));
                hb[u + 3] = __float2half(__expf(-fabsf(w4.w) * dd3));
            }
#pragma unroll
            for (int q = 0; q < 8; q++)
                reinterpret_cast<uint4*>(grow)[q] =
                    reinterpret_cast<uint4*>(hb)[q];
        }
    } else if (MODE == 0) {
        // Q epilogue: fp16 store to g_qh
#pragma unroll
        for (int mf = 0; mf < 4; mf++)
#pragma unroll
            for (int rs = 0; rs < 2; rs++) {
                const int row = rb + mf * 16 + rs * 8;
                __half* orow = g_qh + (size_t)row * NDIM;
#pragma unroll
                for (int nf = 0; nf < 4; nf++) {
                    __half2 h = __floats2half2_rn(acc[mf][nf][rs * 2 + 0],
                                                  acc[mf][nf][rs * 2 + 1]);
                    *reinterpret_cast<__half2*>(&orow[cb + nf * 8]) = h;
                }
            }
    } else {
        float2 bias2[4];
#pragma unroll
        for (int nf = 0; nf < 4; nf++)
            bias2[nf] = *reinterpret_cast<const float2*>(&aux[cb + nf * 8]);
#pragma unroll
        for (int mf = 0; mf < 4; mf++)
#pragma unroll
            for (int rs = 0; rs < 2; rs++) {
                const int row = rb + mf * 16 + rs * 8;
                float* orow = Cext + (size_t)row * NDIM;
#pragma unroll
                for (int nf = 0; nf < 4; nf++) {
                    float2 v;
                    v.x = acc[mf][nf][rs * 2 + 0] + bias2[nf].x;
                    v.y = acc[mf][nf][rs * 2 + 1] + bias2[nf].y;
                    *reinterpret_cast<float2*>(&orow[cb + nf * 8]) = v;
                }
            }
    }
}

// ---------------- merged prep kernel ----------------------------------------
// blocks [0, NDIM): row-wise x prep (fp16 convert + ||x_i||^2, one read of x)
// blocks [NDIM, NDIM+8192): W_out fp32 -> fp16 chunk convert
__global__ void prep_kernel(const float* __restrict__ x,
                            const float* __restrict__ wout)
{
    const int b = blockIdx.x;
    if (b < NDIM) {
        const int row = b;
        const float4* xr = reinterpret_cast<const float4*>(x + (size_t)row * NDIM);
        uint4* hr = reinterpret_cast<uint4*>(g_xh + (size_t)row * NDIM);
        float s = 0.f;
#pragma unroll
        for (int t = 0; t < 2; t++) {
            int i = threadIdx.x + t * 256;           // uint4 index, 2 per thread
            float4 a = xr[2 * i], bb = xr[2 * i + 1];
            s += a.x * a.x + a.y * a.y + a.z * a.z + a.w * a.w
               + bb.x * bb.x + bb.y * bb.y + bb.z * bb.z + bb.w * bb.w;
            __half2 h0 = __floats2half2_rn(a.x, a.y);
            __half2 h1 = __floats2half2_rn(a.z, a.w);
            __half2 h2 = __floats2half2_rn(bb.x, bb.y);
            __half2 h3 = __floats2half2_rn(bb.z, bb.w);
            uint4 o;
            o.x = *reinterpret_cast<uint32_t*>(&h0);
            o.y = *reinterpret_cast<uint32_t*>(&h1);
            o.z = *reinterpret_cast<uint32_t*>(&h2);
            o.w = *reinterpret_cast<uint32_t*>(&h3);
            hr[i] = o;
        }
        __shared__ float red[256];
        red[threadIdx.x] = s;
        __syncthreads();
        for (int off = 128; off > 0; off >>= 1) {
            if (threadIdx.x < off) red[threadIdx.x] += red[threadIdx.x + off];
            __syncthreads();
        }
        if (threadIdx.x == 0) g_sq[row] = red[0];
    } else {
        size_t i = ((size_t)(b - NDIM) * 256 + threadIdx.x) * 8;
        const float4* sp = reinterpret_cast<const float4*>(wout + i);
        float4 a = sp[0], bb = sp[1];
        __half2 h0 = __floats2half2_rn(a.x, a.y);
        __half2 h1 = __floats2half2_rn(a.z, a.w);
        __half2 h2 = __floats2half2_rn(bb.x, bb.y);
        __half2 h3 = __floats2half2_rn(bb.z, bb.w);
        uint4 o;
        o.x = *reinterpret_cast<uint32_t*>(&h0);
        o.y = *reinterpret_cast<uint32_t*>(&h1);
        o.z = *reinterpret_cast<uint32_t*>(&h2);
        o.w = *reinterpret_cast<uint32_t*>(&h3);
        *reinterpret_cast<uint4*>(g_wouth + i) = o;
    }
}

// ---------------------------------------------------------------------------
extern "C" void kernel_launch(void* const* d_in, const int* in_sizes, int n_in,
                              void* d_out, int out_size)
{
    const float* x     = (const float*)d_in[0];
    const float* W_rbf = (const float*)d_in[1];
    const float* W_out = (const float*)d_in[2];
    const float* b_out = (const float*)d_in[3];
    float* out = (float*)d_out;

    static bool attr_done = false;
    if (!attr_done) {
        cudaFuncSetAttribute(hmma_gemm<0>, cudaFuncAttributeMaxDynamicSharedMemorySize, SMEM_TOTAL);
        cudaFuncSetAttribute(hmma_gemm<2>, cudaFuncAttributeMaxDynamicSharedMemorySize, SMEM_TOTAL);
        attr_done = true;
    }

    // merged prep: x row prep (4096 blocks) + W_out convert (8192 blocks)
    prep_kernel<<<NDIM + 8192, 256>>>(x, W_out);

    // fused: gram (528 tri-tiles) + Q = W_out @ x^T (1024 tiles), one launch
    hmma_gemm<0><<<FUSED_BLOCKS, 256, SMEM_TOTAL>>>(W_rbf, nullptr);
    // final: out = NT(gram, Q) + b
    dim3 grid(NDIM / BN, NDIM / BM);   // 32 x 32
    hmma_gemm<2><<<grid, 256, SMEM_TOTAL>>>(b_out, out);
}